// round 10
// baseline (speedup 1.0000x reference)
#include <cuda_runtime.h>
#include <cstdint>

#define T_LEN  4096
#define NTH    256
#define PER    4                  // steps per thread
#define SPLIT  4                  // tiles per sequence
#define TILE_STEPS (NTH * PER)    // 1024
#define PITCH  257                // smem row pitch for output staging (257 % 32 == 1)

#define DTF    (1.0f / 200.0f)
#define DT2H   (DTF * DTF * 0.5f)
#define STEPDT ((float)PER * DTF)

#define MAX_SEQ 1024

// cross-tile exchange buffers (cleared each launch by clear_flags)
__device__ float g_agg[MAX_SEQ * SPLIT * 10];
__device__ int   g_flags[MAX_SEQ * SPLIT];

// scan element: unit quaternion q, v, p.
struct QC { float qw,qx,qy,qz, vx,vy,vz, px,py,pz; };

__device__ __forceinline__ void set_identity(QC& C) {
    C.qw=1.f; C.qx=0.f; C.qy=0.f; C.qz=0.f;
    C.vx=C.vy=C.vz=0.f; C.px=C.py=C.pz=0.f;
}

__device__ __forceinline__ void rot_q(float qw,float qx,float qy,float qz,
                                      float x,float y,float z,
                                      float& rx,float& ry,float& rz) {
    float tx = 2.0f*(qy*z - qz*y);
    float ty = 2.0f*(qz*x - qx*z);
    float tz = 2.0f*(qx*y - qy*x);
    rx = x + qw*tx + (qy*tz - qz*ty);
    ry = y + qw*ty + (qz*tx - qx*tz);
    rz = z + qw*tz + (qx*ty - qy*tx);
}

// C = L compose C (L earlier); span_r = time span covered by C
__device__ __forceinline__ void compose_left(QC& C, const QC& L, float span_r) {
    float qw = L.qw*C.qw - L.qx*C.qx - L.qy*C.qy - L.qz*C.qz;
    float qx = L.qw*C.qx + L.qx*C.qw + L.qy*C.qz - L.qz*C.qy;
    float qy = L.qw*C.qy - L.qx*C.qz + L.qy*C.qw + L.qz*C.qx;
    float qz = L.qw*C.qz + L.qx*C.qy - L.qy*C.qx + L.qz*C.qw;
    float rvx,rvy,rvz; rot_q(L.qw,L.qx,L.qy,L.qz, C.vx,C.vy,C.vz, rvx,rvy,rvz);
    float rpx,rpy,rpz; rot_q(L.qw,L.qx,L.qy,L.qz, C.px,C.py,C.pz, rpx,rpy,rpz);
    C.qw=qw; C.qx=qx; C.qy=qy; C.qz=qz;
    C.vx = L.vx + rvx;  C.vy = L.vy + rvy;  C.vz = L.vz + rvz;
    C.px = L.px + L.vx*span_r + rpx;
    C.py = L.py + L.vy*span_r + rpy;
    C.pz = L.pz + L.vz*span_r + rpz;
}

__device__ __forceinline__ void step_q(QC& C, float wx,float wy,float wz,
                                       float ax,float ay,float az) {
    float n2 = fmaf(wx,wx, fmaf(wy,wy, wz*wz));
    float h2 = n2 * (0.25f * DTF * DTF);
    float dqw = 1.0f - h2*(0.5f - h2*(1.0f/24.0f));
    float s   = (0.5f*DTF) * (1.0f - h2*(1.0f/6.0f - h2*(1.0f/120.0f)));
    float dqx = wx*s, dqy = wy*s, dqz = wz*s;

    float qw = C.qw*dqw - C.qx*dqx - C.qy*dqy - C.qz*dqz;
    float qx = C.qw*dqx + C.qx*dqw + C.qy*dqz - C.qz*dqy;
    float qy = C.qw*dqy - C.qx*dqz + C.qy*dqw + C.qz*dqx;
    float qz = C.qw*dqz + C.qx*dqy - C.qy*dqx + C.qz*dqw;
    C.qw=qw; C.qx=qx; C.qy=qy; C.qz=qz;

    float Rax,Ray,Raz; rot_q(qw,qx,qy,qz, ax,ay,az, Rax,Ray,Raz);

    C.vx += Rax*DTF; C.vy += Ray*DTF; C.vz += Raz*DTF;
    C.px += C.vx*DTF + Rax*DT2H;
    C.py += C.vy*DTF + Ray*DT2H;
    C.pz += C.vz*DTF + Raz*DT2H;
}

__device__ __forceinline__ QC shup(const QC& c, int d) {
    QC r;
    r.qw=__shfl_up_sync(0xffffffffu,c.qw,d);
    r.qx=__shfl_up_sync(0xffffffffu,c.qx,d);
    r.qy=__shfl_up_sync(0xffffffffu,c.qy,d);
    r.qz=__shfl_up_sync(0xffffffffu,c.qz,d);
    r.vx=__shfl_up_sync(0xffffffffu,c.vx,d);
    r.vy=__shfl_up_sync(0xffffffffu,c.vy,d);
    r.vz=__shfl_up_sync(0xffffffffu,c.vz,d);
    r.px=__shfl_up_sync(0xffffffffu,c.px,d);
    r.py=__shfl_up_sync(0xffffffffu,c.py,d);
    r.pz=__shfl_up_sync(0xffffffffu,c.pz,d);
    return r;
}

__device__ __forceinline__ void store_qc(float* m, const QC& C) {
    m[0]=C.qw; m[1]=C.qx; m[2]=C.qy; m[3]=C.qz;
    m[4]=C.vx; m[5]=C.vy; m[6]=C.vz;
    m[7]=C.px; m[8]=C.py; m[9]=C.pz;
}
__device__ __forceinline__ void load_qc(const float* m, QC& C) {
    C.qw=m[0]; C.qx=m[1]; C.qy=m[2]; C.qz=m[3];
    C.vx=m[4]; C.vy=m[5]; C.vz=m[6];
    C.px=m[7]; C.py=m[8]; C.pz=m[9];
}

__global__ void clear_flags(int n) {
    int i = blockIdx.x * blockDim.x + threadIdx.x;
    if (i < n) g_flags[i] = 0;
}

__global__ void __launch_bounds__(NTH, 3)
preint_kernel(const float* __restrict__ in, float* __restrict__ out) {
    __shared__ float s_buf[32 * PITCH];   // output staging (2 steps x 16ch x 256 owners)
    __shared__ float s_w[8 * 11];         // warp aggregates / prefixes
    __shared__ float s_prev[10];          // look-back aggregate from tile rr-1

    const int tid  = threadIdx.x;
    const int lane = tid & 31;
    const int wid  = tid >> 5;
    const int seq  = blockIdx.x >> 2;     // sequence index
    const int rr   = blockIdx.x & 3;      // tile rank within sequence
    const int gidx = seq * SPLIT + rr;

    // ---------------- Load input ONCE into registers (6 float4 per thread) ----------------
    const float4* ip = (const float4*)in
        + (size_t)seq * (T_LEN * 6 / 4) + (size_t)rr * (TILE_STEPS * 6 / 4)
        + (size_t)tid * (PER * 6 / 4);
    float4 d[6];
#pragma unroll
    for (int i = 0; i < 6; i++) d[i] = ip[i];

    // ---------------- Phase 1: thread-local aggregate over 4 steps ----------------
    QC C;
    set_identity(C);
#pragma unroll
    for (int g = 0; g < 2; g++) {
        float4 a0 = d[3*g], a1 = d[3*g+1], a2 = d[3*g+2];
        step_q(C, a0.x, a0.y, a0.z, a0.w, a1.x, a1.y);
        step_q(C, a1.z, a1.w, a2.x, a2.y, a2.z, a2.w);
    }

    // ---------------- Intra-warp inclusive scan (shuffles) ----------------
#pragma unroll
    for (int dd = 1; dd < 32; dd <<= 1) {
        QC L = shup(C, dd);
        if (lane >= dd) compose_left(C, L, (float)dd * STEPDT);
    }
    if (lane == 31) store_qc(s_w + wid * 11, C);
    __syncthreads();

    // ---------------- Inter-warp scan of 8 aggregates (warp 0) ----------------
    // warp 1 concurrently polls the look-back aggregate of tile rr-1
    if (wid == 0) {
        QC A;
        if (lane < 8) load_qc(s_w + lane * 11, A);
        else          set_identity(A);
#pragma unroll
        for (int dd = 1; dd < 8; dd <<= 1) {
            QC L = shup(A, dd);
            if (lane >= dd && lane < 8) compose_left(A, L, (float)(dd * 32) * STEPDT);
        }
        if (lane < 8) store_qc(s_w + lane * 11, A);
    } else if (wid == 1 && lane == 0 && rr > 0) {
        int* flag = &g_flags[gidx - 1];
        while (atomicAdd(flag, 0) == 0) { __nanosleep(64); }
        __threadfence();
        const float* src = g_agg + (size_t)(gidx - 1) * 10;
#pragma unroll
        for (int i = 0; i < 10; i++) s_prev[i] = src[i];
    }
    __syncthreads();

    // ---------------- Publish inclusive-from-0 aggregate (tid 0, tiles 0..2) ----------------
    if (tid == 0 && rr < SPLIT - 1) {
        QC T;
        load_qc(s_w + 7 * 11, T);                 // this tile's total
        if (rr > 0) {
            QC P; load_qc(s_prev, P);
            compose_left(T, P, (float)TILE_STEPS * DTF);  // T = P o T
        }
        float* dst = g_agg + (size_t)gidx * 10;
        store_qc(dst, T);
        __threadfence();
        atomicExch(&g_flags[gidx], 1);
    }

    // ---------------- Per-thread exclusive prefix (within tile, then global) --------------
    {
        QC E = shup(C, 1);
        if (lane == 0) set_identity(E);
        QC W;
        if (wid == 0) set_identity(W);
        else          load_qc(s_w + (wid - 1) * 11, W);
        compose_left(E, W, (float)(lane * PER) * DTF);
        if (rr > 0) {
            QC P; load_qc(s_prev, P);
            compose_left(E, P, (float)(tid * PER) * DTF);
        }
        C = E;
    }

    // ---------------- Phase 2: replay from registers, staged + coalesced output ------------
    float4* out4 = (float4*)out
        + (size_t)seq * (T_LEN * 4) + (size_t)rr * (TILE_STEPS * 4);

#pragma unroll
    for (int g = 0; g < 2; g++) {
        float4 a0 = d[3*g], a1 = d[3*g+1], a2 = d[3*g+2];
        float wxs[2] = {a0.x, a1.z};
        float wys[2] = {a0.y, a1.w};
        float wzs[2] = {a0.z, a2.x};
        float axs[2] = {a0.w, a2.y};
        float ays[2] = {a1.x, a2.z};
        float azs[2] = {a1.y, a2.w};

#pragma unroll
        for (int k = 0; k < 2; k++) {
            step_q(C, wxs[k], wys[k], wzs[k], axs[k], ays[k], azs[k]);

            // output quaternion = carry, renormalized, sign-fixed (qw >= 0)
            float n  = fmaf(C.qw,C.qw, fmaf(C.qx,C.qx, fmaf(C.qy,C.qy, C.qz*C.qz)));
            float rn = rsqrtf(n);
            rn = (C.qw < 0.0f) ? -rn : rn;
            float qw = C.qw*rn, qx = C.qx*rn, qy = C.qy*rn, qz = C.qz*rn;

            float* dst = s_buf + (k * 16) * PITCH + tid;
            dst[0*PITCH]  = wxs[k]; dst[1*PITCH]  = wys[k]; dst[2*PITCH]  = wzs[k];
            dst[3*PITCH]  = axs[k]; dst[4*PITCH]  = ays[k]; dst[5*PITCH]  = azs[k];
            dst[6*PITCH]  = C.px;   dst[7*PITCH]  = C.py;   dst[8*PITCH]  = C.pz;
            dst[9*PITCH]  = qw;     dst[10*PITCH] = qx;     dst[11*PITCH] = qy;
            dst[12*PITCH] = qz;
            dst[13*PITCH] = C.vx;   dst[14*PITCH] = C.vy;   dst[15*PITCH] = C.vz;
        }
        __syncthreads();

        // coalesced flush: 2 steps x 256 owners = 2048 float4, 8 per thread
#pragma unroll
        for (int r = 0; r < 8; r++) {
            int f  = tid + NTH * r;
            int o  = f >> 3;
            int mq = f & 7;
            const float* s = s_buf + (mq * 4) * PITCH + o;
            float4 v = make_float4(s[0*PITCH], s[1*PITCH], s[2*PITCH], s[3*PITCH]);
            out4[(size_t)o * (PER * 4) + g * 8 + mq] = v;
        }
        __syncthreads();
    }
}

extern "C" void kernel_launch(void* const* d_in, const int* in_sizes, int n_in,
                              void* d_out, int out_size) {
    const float* in = (const float*)d_in[0];
    float* out = (float*)d_out;
    int Bn = in_sizes[0] / (T_LEN * 6);   // 512 for the reference shapes
    int nflags = Bn * SPLIT;
    clear_flags<<<(nflags + 255) / 256, 256>>>(nflags);
    preint_kernel<<<Bn * SPLIT, NTH>>>(in, out);
}

// round 11
// speedup vs baseline: 1.1225x; 1.1225x over previous
#include <cuda_runtime.h>
#include <cstdint>

#define T_LEN  4096
#define NTH    256
#define PER    4                  // steps per thread
#define SPLIT  4                  // tiles per sequence
#define TILE_STEPS (NTH * PER)    // 1024
#define PITCH  257                // smem row pitch for output staging (257 % 32 == 1)

#define DTF    (1.0f / 200.0f)
#define DT2H   (DTF * DTF * 0.5f)
#define STEPDT ((float)PER * DTF)

#define MAX_SEQ 1024

// cross-tile exchange buffers. flags are zero-initialized at module load and
// reset to zero by the LAST reader each launch -> no clearing kernel needed.
__device__ float g_agg[MAX_SEQ * SPLIT * 10];
__device__ int   g_flags[MAX_SEQ * SPLIT];

// scan element: unit quaternion q, v, p.
struct QC { float qw,qx,qy,qz, vx,vy,vz, px,py,pz; };

__device__ __forceinline__ void set_identity(QC& C) {
    C.qw=1.f; C.qx=0.f; C.qy=0.f; C.qz=0.f;
    C.vx=C.vy=C.vz=0.f; C.px=C.py=C.pz=0.f;
}

__device__ __forceinline__ void rot_q(float qw,float qx,float qy,float qz,
                                      float x,float y,float z,
                                      float& rx,float& ry,float& rz) {
    float tx = 2.0f*(qy*z - qz*y);
    float ty = 2.0f*(qz*x - qx*z);
    float tz = 2.0f*(qx*y - qy*x);
    rx = x + qw*tx + (qy*tz - qz*ty);
    ry = y + qw*ty + (qz*tx - qx*tz);
    rz = z + qw*tz + (qx*ty - qy*tx);
}

// C = L compose C (L earlier); span_r = time span covered by C
__device__ __forceinline__ void compose_left(QC& C, const QC& L, float span_r) {
    float qw = L.qw*C.qw - L.qx*C.qx - L.qy*C.qy - L.qz*C.qz;
    float qx = L.qw*C.qx + L.qx*C.qw + L.qy*C.qz - L.qz*C.qy;
    float qy = L.qw*C.qy - L.qx*C.qz + L.qy*C.qw + L.qz*C.qx;
    float qz = L.qw*C.qz + L.qx*C.qy - L.qy*C.qx + L.qz*C.qw;
    float rvx,rvy,rvz; rot_q(L.qw,L.qx,L.qy,L.qz, C.vx,C.vy,C.vz, rvx,rvy,rvz);
    float rpx,rpy,rpz; rot_q(L.qw,L.qx,L.qy,L.qz, C.px,C.py,C.pz, rpx,rpy,rpz);
    C.qw=qw; C.qx=qx; C.qy=qy; C.qz=qz;
    C.vx = L.vx + rvx;  C.vy = L.vy + rvy;  C.vz = L.vz + rvz;
    C.px = L.px + L.vx*span_r + rpx;
    C.py = L.py + L.vy*span_r + rpy;
    C.pz = L.pz + L.vz*span_r + rpz;
}

__device__ __forceinline__ void step_q(QC& C, float wx,float wy,float wz,
                                       float ax,float ay,float az) {
    float n2 = fmaf(wx,wx, fmaf(wy,wy, wz*wz));
    float h2 = n2 * (0.25f * DTF * DTF);
    float dqw = 1.0f - h2*(0.5f - h2*(1.0f/24.0f));
    float s   = (0.5f*DTF) * (1.0f - h2*(1.0f/6.0f - h2*(1.0f/120.0f)));
    float dqx = wx*s, dqy = wy*s, dqz = wz*s;

    float qw = C.qw*dqw - C.qx*dqx - C.qy*dqy - C.qz*dqz;
    float qx = C.qw*dqx + C.qx*dqw + C.qy*dqz - C.qz*dqy;
    float qy = C.qw*dqy - C.qx*dqz + C.qy*dqw + C.qz*dqx;
    float qz = C.qw*dqz + C.qx*dqy - C.qy*dqx + C.qz*dqw;
    C.qw=qw; C.qx=qx; C.qy=qy; C.qz=qz;

    float Rax,Ray,Raz; rot_q(qw,qx,qy,qz, ax,ay,az, Rax,Ray,Raz);

    C.vx += Rax*DTF; C.vy += Ray*DTF; C.vz += Raz*DTF;
    C.px += C.vx*DTF + Rax*DT2H;
    C.py += C.vy*DTF + Ray*DT2H;
    C.pz += C.vz*DTF + Raz*DT2H;
}

__device__ __forceinline__ QC shup(const QC& c, int d) {
    QC r;
    r.qw=__shfl_up_sync(0xffffffffu,c.qw,d);
    r.qx=__shfl_up_sync(0xffffffffu,c.qx,d);
    r.qy=__shfl_up_sync(0xffffffffu,c.qy,d);
    r.qz=__shfl_up_sync(0xffffffffu,c.qz,d);
    r.vx=__shfl_up_sync(0xffffffffu,c.vx,d);
    r.vy=__shfl_up_sync(0xffffffffu,c.vy,d);
    r.vz=__shfl_up_sync(0xffffffffu,c.vz,d);
    r.px=__shfl_up_sync(0xffffffffu,c.px,d);
    r.py=__shfl_up_sync(0xffffffffu,c.py,d);
    r.pz=__shfl_up_sync(0xffffffffu,c.pz,d);
    return r;
}

__device__ __forceinline__ void store_qc(float* m, const QC& C) {
    m[0]=C.qw; m[1]=C.qx; m[2]=C.qy; m[3]=C.qz;
    m[4]=C.vx; m[5]=C.vy; m[6]=C.vz;
    m[7]=C.px; m[8]=C.py; m[9]=C.pz;
}
__device__ __forceinline__ void load_qc(const float* m, QC& C) {
    C.qw=m[0]; C.qx=m[1]; C.qy=m[2]; C.qz=m[3];
    C.vx=m[4]; C.vy=m[5]; C.vz=m[6];
    C.px=m[7]; C.py=m[8]; C.pz=m[9];
}

__global__ void __launch_bounds__(NTH, 3)
preint_kernel(const float* __restrict__ in, float* __restrict__ out) {
    __shared__ float s_buf[32 * PITCH];   // output staging (2 steps x 16ch x 256 owners)
    __shared__ float s_w[8 * 11];         // warp aggregates / prefixes
    __shared__ float s_pre[SPLIT * 10];   // raw predecessor tile aggregates
    __shared__ float s_prev[10];          // composed global prefix of previous tiles

    const int tid  = threadIdx.x;
    const int lane = tid & 31;
    const int wid  = tid >> 5;
    const int seq  = blockIdx.x >> 2;     // sequence index
    const int rr   = blockIdx.x & 3;      // tile rank within sequence
    const int gidx = seq * SPLIT + rr;

    // ---------------- Load input ONCE into registers (6 float4 per thread) ----------------
    const float4* ip = (const float4*)in
        + (size_t)seq * (T_LEN * 6 / 4) + (size_t)rr * (TILE_STEPS * 6 / 4)
        + (size_t)tid * (PER * 6 / 4);
    float4 d[6];
#pragma unroll
    for (int i = 0; i < 6; i++) d[i] = ip[i];

    // ---------------- Phase 1: thread-local aggregate over 4 steps ----------------
    QC C;
    set_identity(C);
#pragma unroll
    for (int g = 0; g < 2; g++) {
        float4 a0 = d[3*g], a1 = d[3*g+1], a2 = d[3*g+2];
        step_q(C, a0.x, a0.y, a0.z, a0.w, a1.x, a1.y);
        step_q(C, a1.z, a1.w, a2.x, a2.y, a2.z, a2.w);
    }

    // ---------------- Intra-warp inclusive scan (shuffles) ----------------
#pragma unroll
    for (int dd = 1; dd < 32; dd <<= 1) {
        QC L = shup(C, dd);
        if (lane >= dd) compose_left(C, L, (float)dd * STEPDT);
    }
    if (lane == 31) store_qc(s_w + wid * 11, C);
    __syncthreads();

    // ---------------- Inter-warp scan (warp 0) || flattened look-back (warp 1) -------------
    if (wid == 0) {
        QC A;
        if (lane < 8) load_qc(s_w + lane * 11, A);
        else          set_identity(A);
#pragma unroll
        for (int dd = 1; dd < 8; dd <<= 1) {
            QC L = shup(A, dd);
            if (lane >= dd && lane < 8) compose_left(A, L, (float)(dd * 32) * STEPDT);
        }
        if (lane < 8) store_qc(s_w + lane * 11, A);
        // publish tile-LOCAL total (lane 7 holds it) immediately — no forwarding chain
        if (lane == 7 && rr != SPLIT - 1) {
            float* dst = g_agg + (size_t)gidx * 10;
            store_qc(dst, A);
            __threadfence();
            atomicExch(&g_flags[gidx], 1);
        }
    } else if (wid == 1) {
        // lanes 0..rr-1 each poll ONE predecessor in parallel (no chain)
        if (lane < rr) {
            int  src  = seq * SPLIT + lane;
            int* flag = &g_flags[src];
            while (atomicAdd(flag, 0) == 0) { __nanosleep(32); }
            __threadfence();
            const float* sp = g_agg + (size_t)src * 10;
#pragma unroll
            for (int i = 0; i < 10; i++) s_pre[lane * 10 + i] = sp[i];
            // last-reader reset: flag of rank `lane` has SPLIT-1-lane readers
            int old = atomicAdd(flag, 1);
            if (old == SPLIT - 1 - lane) atomicExch(flag, 0);
        }
        __syncwarp();
        if (lane == 0 && rr > 0) {
            QC P;
            load_qc(s_pre + (rr - 1) * 10, P);          // latest predecessor
            for (int j = rr - 2; j >= 0; j--) {
                QC L; load_qc(s_pre + j * 10, L);
                compose_left(P, L, (float)(rr - 1 - j) * TILE_STEPS * DTF);
            }
            store_qc(s_prev, P);
        }
    }
    __syncthreads();

    // ---------------- Per-thread exclusive prefix (within tile, then global) --------------
    {
        QC E = shup(C, 1);
        if (lane == 0) set_identity(E);
        QC W;
        if (wid == 0) set_identity(W);
        else          load_qc(s_w + (wid - 1) * 11, W);
        compose_left(E, W, (float)(lane * PER) * DTF);
        if (rr > 0) {
            QC P; load_qc(s_prev, P);
            compose_left(E, P, (float)(tid * PER) * DTF);
        }
        C = E;
    }

    // ---------------- Phase 2: replay from registers, staged + coalesced output ------------
    float4* out4 = (float4*)out
        + (size_t)seq * (T_LEN * 4) + (size_t)rr * (TILE_STEPS * 4);

#pragma unroll
    for (int g = 0; g < 2; g++) {
        float4 a0 = d[3*g], a1 = d[3*g+1], a2 = d[3*g+2];
        float wxs[2] = {a0.x, a1.z};
        float wys[2] = {a0.y, a1.w};
        float wzs[2] = {a0.z, a2.x};
        float axs[2] = {a0.w, a2.y};
        float ays[2] = {a1.x, a2.z};
        float azs[2] = {a1.y, a2.w};

#pragma unroll
        for (int k = 0; k < 2; k++) {
            step_q(C, wxs[k], wys[k], wzs[k], axs[k], ays[k], azs[k]);

            // output quaternion = carry, renormalized, sign-fixed (qw >= 0)
            float n  = fmaf(C.qw,C.qw, fmaf(C.qx,C.qx, fmaf(C.qy,C.qy, C.qz*C.qz)));
            float rn = rsqrtf(n);
            rn = (C.qw < 0.0f) ? -rn : rn;
            float qw = C.qw*rn, qx = C.qx*rn, qy = C.qy*rn, qz = C.qz*rn;

            float* dst = s_buf + (k * 16) * PITCH + tid;
            dst[0*PITCH]  = wxs[k]; dst[1*PITCH]  = wys[k]; dst[2*PITCH]  = wzs[k];
            dst[3*PITCH]  = axs[k]; dst[4*PITCH]  = ays[k]; dst[5*PITCH]  = azs[k];
            dst[6*PITCH]  = C.px;   dst[7*PITCH]  = C.py;   dst[8*PITCH]  = C.pz;
            dst[9*PITCH]  = qw;     dst[10*PITCH] = qx;     dst[11*PITCH] = qy;
            dst[12*PITCH] = qz;
            dst[13*PITCH] = C.vx;   dst[14*PITCH] = C.vy;   dst[15*PITCH] = C.vz;
        }
        __syncthreads();

        // coalesced flush: 2 steps x 256 owners = 2048 float4, 8 per thread
#pragma unroll
        for (int r = 0; r < 8; r++) {
            int f  = tid + NTH * r;
            int o  = f >> 3;
            int mq = f & 7;
            const float* s = s_buf + (mq * 4) * PITCH + o;
            float4 v = make_float4(s[0*PITCH], s[1*PITCH], s[2*PITCH], s[3*PITCH]);
            out4[(size_t)o * (PER * 4) + g * 8 + mq] = v;
        }
        __syncthreads();
    }
}

extern "C" void kernel_launch(void* const* d_in, const int* in_sizes, int n_in,
                              void* d_out, int out_size) {
    const float* in = (const float*)d_in[0];
    float* out = (float*)d_out;
    int Bn = in_sizes[0] / (T_LEN * 6);   // 512 for the reference shapes
    preint_kernel<<<Bn * SPLIT, NTH>>>(in, out);
}

// round 12
// speedup vs baseline: 1.2115x; 1.0792x over previous
#include <cuda_runtime.h>
#include <cstdint>

#define T_LEN  4096
#define NTH    256
#define PER    4                  // steps per thread
#define SPLIT  4                  // tiles per sequence
#define TILE_STEPS (NTH * PER)    // 1024
#define PITCH  257                // smem row pitch for output staging (257 % 32 == 1)

#define DTF    (1.0f / 200.0f)
#define DT2H   (DTF * DTF * 0.5f)
#define STEPDT ((float)PER * DTF)

#define MAX_SEQ 1024

// cross-tile exchange buffers. flags are zero-initialized at module load and
// reset to zero by the LAST reader each launch -> no clearing kernel needed.
__device__ float g_agg[MAX_SEQ * SPLIT * 10];
__device__ int   g_flags[MAX_SEQ * SPLIT];

// scan element: unit quaternion q, v, p.
struct QC { float qw,qx,qy,qz, vx,vy,vz, px,py,pz; };

__device__ __forceinline__ void set_identity(QC& C) {
    C.qw=1.f; C.qx=0.f; C.qy=0.f; C.qz=0.f;
    C.vx=C.vy=C.vz=0.f; C.px=C.py=C.pz=0.f;
}

__device__ __forceinline__ void rot_q(float qw,float qx,float qy,float qz,
                                      float x,float y,float z,
                                      float& rx,float& ry,float& rz) {
    float tx = 2.0f*(qy*z - qz*y);
    float ty = 2.0f*(qz*x - qx*z);
    float tz = 2.0f*(qx*y - qy*x);
    rx = x + qw*tx + (qy*tz - qz*ty);
    ry = y + qw*ty + (qz*tx - qx*tz);
    rz = z + qw*tz + (qx*ty - qy*tx);
}

// C = L compose C (L earlier); span_r = time span covered by C
__device__ __forceinline__ void compose_left(QC& C, const QC& L, float span_r) {
    float qw = L.qw*C.qw - L.qx*C.qx - L.qy*C.qy - L.qz*C.qz;
    float qx = L.qw*C.qx + L.qx*C.qw + L.qy*C.qz - L.qz*C.qy;
    float qy = L.qw*C.qy - L.qx*C.qz + L.qy*C.qw + L.qz*C.qx;
    float qz = L.qw*C.qz + L.qx*C.qy - L.qy*C.qx + L.qz*C.qw;
    float rvx,rvy,rvz; rot_q(L.qw,L.qx,L.qy,L.qz, C.vx,C.vy,C.vz, rvx,rvy,rvz);
    float rpx,rpy,rpz; rot_q(L.qw,L.qx,L.qy,L.qz, C.px,C.py,C.pz, rpx,rpy,rpz);
    C.qw=qw; C.qx=qx; C.qy=qy; C.qz=qz;
    C.vx = L.vx + rvx;  C.vy = L.vy + rvy;  C.vz = L.vz + rvz;
    C.px = L.px + L.vx*span_r + rpx;
    C.py = L.py + L.vy*span_r + rpy;
    C.pz = L.pz + L.vz*span_r + rpz;
}

__device__ __forceinline__ void step_q(QC& C, float wx,float wy,float wz,
                                       float ax,float ay,float az) {
    float n2 = fmaf(wx,wx, fmaf(wy,wy, wz*wz));
    float h2 = n2 * (0.25f * DTF * DTF);
    float dqw = 1.0f - h2*(0.5f - h2*(1.0f/24.0f));
    float s   = (0.5f*DTF) * (1.0f - h2*(1.0f/6.0f - h2*(1.0f/120.0f)));
    float dqx = wx*s, dqy = wy*s, dqz = wz*s;

    float qw = C.qw*dqw - C.qx*dqx - C.qy*dqy - C.qz*dqz;
    float qx = C.qw*dqx + C.qx*dqw + C.qy*dqz - C.qz*dqy;
    float qy = C.qw*dqy - C.qx*dqz + C.qy*dqw + C.qz*dqx;
    float qz = C.qw*dqz + C.qx*dqy - C.qy*dqx + C.qz*dqw;
    C.qw=qw; C.qx=qx; C.qy=qy; C.qz=qz;

    float Rax,Ray,Raz; rot_q(qw,qx,qy,qz, ax,ay,az, Rax,Ray,Raz);

    C.vx += Rax*DTF; C.vy += Ray*DTF; C.vz += Raz*DTF;
    C.px += C.vx*DTF + Rax*DT2H;
    C.py += C.vy*DTF + Ray*DT2H;
    C.pz += C.vz*DTF + Raz*DT2H;
}

__device__ __forceinline__ QC shup(const QC& c, int d) {
    QC r;
    r.qw=__shfl_up_sync(0xffffffffu,c.qw,d);
    r.qx=__shfl_up_sync(0xffffffffu,c.qx,d);
    r.qy=__shfl_up_sync(0xffffffffu,c.qy,d);
    r.qz=__shfl_up_sync(0xffffffffu,c.qz,d);
    r.vx=__shfl_up_sync(0xffffffffu,c.vx,d);
    r.vy=__shfl_up_sync(0xffffffffu,c.vy,d);
    r.vz=__shfl_up_sync(0xffffffffu,c.vz,d);
    r.px=__shfl_up_sync(0xffffffffu,c.px,d);
    r.py=__shfl_up_sync(0xffffffffu,c.py,d);
    r.pz=__shfl_up_sync(0xffffffffu,c.pz,d);
    return r;
}

__device__ __forceinline__ void store_qc(float* m, const QC& C) {
    m[0]=C.qw; m[1]=C.qx; m[2]=C.qy; m[3]=C.qz;
    m[4]=C.vx; m[5]=C.vy; m[6]=C.vz;
    m[7]=C.px; m[8]=C.py; m[9]=C.pz;
}
__device__ __forceinline__ void load_qc(const float* m, QC& C) {
    C.qw=m[0]; C.qx=m[1]; C.qy=m[2]; C.qz=m[3];
    C.vx=m[4]; C.vy=m[5]; C.vz=m[6];
    C.px=m[7]; C.py=m[8]; C.pz=m[9];
}

__global__ void __launch_bounds__(NTH, 4)
preint_kernel(const float* __restrict__ in, float* __restrict__ out) {
    __shared__ float s_buf[32 * PITCH];   // output staging (2 steps x 16ch x 256 owners)
    __shared__ float s_w[8 * 11];         // warp aggregates / prefixes
    __shared__ float s_pre[SPLIT * 10];   // raw predecessor tile aggregates
    __shared__ float s_prev[10];          // composed global prefix of previous tiles

    const int tid  = threadIdx.x;
    const int lane = tid & 31;
    const int wid  = tid >> 5;
    const int seq  = blockIdx.x >> 2;     // sequence index
    const int rr   = blockIdx.x & 3;      // tile rank within sequence
    const int gidx = seq * SPLIT + rr;

    const float4* ip = (const float4*)in
        + (size_t)seq * (T_LEN * 6 / 4) + (size_t)rr * (TILE_STEPS * 6 / 4)
        + (size_t)tid * (PER * 6 / 4);

    // ---------------- Phase 1: two independent 2-step chains, then merge (ILP x2) ----------
    QC C;           // chain A: steps 0-1
    QC C2;          // chain B: steps 2-3
    set_identity(C);
    set_identity(C2);
    {
        float4 a0 = __ldg(ip+0), a1 = __ldg(ip+1), a2 = __ldg(ip+2);
        float4 b0 = __ldg(ip+3), b1 = __ldg(ip+4), b2 = __ldg(ip+5);
        step_q(C,  a0.x, a0.y, a0.z, a0.w, a1.x, a1.y);
        step_q(C2, b0.x, b0.y, b0.z, b0.w, b1.x, b1.y);
        step_q(C,  a1.z, a1.w, a2.x, a2.y, a2.z, a2.w);
        step_q(C2, b1.z, b1.w, b2.x, b2.y, b2.z, b2.w);
        // merge: A earlier, B later -> total = A o B
        compose_left(C2, C, 2.0f * DTF);
        C = C2;
    }

    // ---------------- Intra-warp inclusive scan (shuffles) ----------------
#pragma unroll
    for (int dd = 1; dd < 32; dd <<= 1) {
        QC L = shup(C, dd);
        if (lane >= dd) compose_left(C, L, (float)dd * STEPDT);
    }
    if (lane == 31) store_qc(s_w + wid * 11, C);
    __syncthreads();

    // ---------------- Inter-warp scan (warp 0) || flattened look-back (warp 1) -------------
    if (wid == 0) {
        QC A;
        if (lane < 8) load_qc(s_w + lane * 11, A);
        else          set_identity(A);
#pragma unroll
        for (int dd = 1; dd < 8; dd <<= 1) {
            QC L = shup(A, dd);
            if (lane >= dd && lane < 8) compose_left(A, L, (float)(dd * 32) * STEPDT);
        }
        if (lane < 8) store_qc(s_w + lane * 11, A);
        // publish tile-LOCAL total (lane 7 holds it) immediately — no forwarding chain
        if (lane == 7 && rr != SPLIT - 1) {
            float* dst = g_agg + (size_t)gidx * 10;
            store_qc(dst, A);
            __threadfence();
            atomicExch(&g_flags[gidx], 1);
        }
    } else if (wid == 1) {
        // lanes 0..rr-1 each poll ONE predecessor in parallel (no chain)
        if (lane < rr) {
            int  src  = seq * SPLIT + lane;
            int* flag = &g_flags[src];
            while (atomicAdd(flag, 0) == 0) { __nanosleep(32); }
            __threadfence();
            const float* sp = g_agg + (size_t)src * 10;
#pragma unroll
            for (int i = 0; i < 10; i++) s_pre[lane * 10 + i] = sp[i];
            // last-reader reset: flag of rank `lane` has SPLIT-1-lane readers
            int old = atomicAdd(flag, 1);
            if (old == SPLIT - 1 - lane) atomicExch(flag, 0);
        }
        __syncwarp();
        if (lane == 0 && rr > 0) {
            QC P;
            load_qc(s_pre + (rr - 1) * 10, P);          // latest predecessor
            for (int j = rr - 2; j >= 0; j--) {
                QC L; load_qc(s_pre + j * 10, L);
                compose_left(P, L, (float)(rr - 1 - j) * TILE_STEPS * DTF);
            }
            store_qc(s_prev, P);
        }
    }
    __syncthreads();

    // ---------------- Per-thread exclusive prefix (within tile, then global) --------------
    {
        QC E = shup(C, 1);
        if (lane == 0) set_identity(E);
        QC W;
        if (wid == 0) set_identity(W);
        else          load_qc(s_w + (wid - 1) * 11, W);
        compose_left(E, W, (float)(lane * PER) * DTF);
        if (rr > 0) {
            QC P; load_qc(s_prev, P);
            compose_left(E, P, (float)(tid * PER) * DTF);
        }
        C = E;
    }

    // ---------------- Phase 2: replay (input re-read, L2-hot), coalesced output ------------
    float4* out4 = (float4*)out
        + (size_t)seq * (T_LEN * 4) + (size_t)rr * (TILE_STEPS * 4);

#pragma unroll
    for (int g = 0; g < 2; g++) {
        float4 a0 = __ldg(ip + 3*g + 0);
        float4 a1 = __ldg(ip + 3*g + 1);
        float4 a2 = __ldg(ip + 3*g + 2);
        float wxs[2] = {a0.x, a1.z};
        float wys[2] = {a0.y, a1.w};
        float wzs[2] = {a0.z, a2.x};
        float axs[2] = {a0.w, a2.y};
        float ays[2] = {a1.x, a2.z};
        float azs[2] = {a1.y, a2.w};

#pragma unroll
        for (int k = 0; k < 2; k++) {
            step_q(C, wxs[k], wys[k], wzs[k], axs[k], ays[k], azs[k]);

            // output quaternion = carry, renormalized, sign-fixed (qw >= 0)
            float n  = fmaf(C.qw,C.qw, fmaf(C.qx,C.qx, fmaf(C.qy,C.qy, C.qz*C.qz)));
            float rn = rsqrtf(n);
            rn = (C.qw < 0.0f) ? -rn : rn;
            float qw = C.qw*rn, qx = C.qx*rn, qy = C.qy*rn, qz = C.qz*rn;

            float* dst = s_buf + (k * 16) * PITCH + tid;
            dst[0*PITCH]  = wxs[k]; dst[1*PITCH]  = wys[k]; dst[2*PITCH]  = wzs[k];
            dst[3*PITCH]  = axs[k]; dst[4*PITCH]  = ays[k]; dst[5*PITCH]  = azs[k];
            dst[6*PITCH]  = C.px;   dst[7*PITCH]  = C.py;   dst[8*PITCH]  = C.pz;
            dst[9*PITCH]  = qw;     dst[10*PITCH] = qx;     dst[11*PITCH] = qy;
            dst[12*PITCH] = qz;
            dst[13*PITCH] = C.vx;   dst[14*PITCH] = C.vy;   dst[15*PITCH] = C.vz;
        }
        __syncthreads();

        // coalesced flush: 2 steps x 256 owners = 2048 float4, 8 per thread
#pragma unroll
        for (int r = 0; r < 8; r++) {
            int f  = tid + NTH * r;
            int o  = f >> 3;
            int mq = f & 7;
            const float* s = s_buf + (mq * 4) * PITCH + o;
            float4 v = make_float4(s[0*PITCH], s[1*PITCH], s[2*PITCH], s[3*PITCH]);
            out4[(size_t)o * (PER * 4) + g * 8 + mq] = v;
        }
        __syncthreads();
    }
}

extern "C" void kernel_launch(void* const* d_in, const int* in_sizes, int n_in,
                              void* d_out, int out_size) {
    const float* in = (const float*)d_in[0];
    float* out = (float*)d_out;
    int Bn = in_sizes[0] / (T_LEN * 6);   // 512 for the reference shapes
    preint_kernel<<<Bn * SPLIT, NTH>>>(in, out);
}